// round 1
// baseline (speedup 1.0000x reference)
#include <cuda_runtime.h>
#include <math.h>

#define BB 8
#define GG 16
#define PP 64
#define IMH 640
#define IMW 640
#define SZ 32
#define NPIX (SZ*SZ)
#define WIN 11

// Scratch (no cudaMalloc allowed)
__device__ float d_gt_patch[BB*GG*3*NPIX];   // 1.5 MB
__device__ float d_pr_patch[BB*PP*3*NPIX];   // 6 MB
__device__ double d_total;
__device__ double d_cnt;
__device__ float d_gw[WIN];

// ---------------- init: zero accumulators, build normalized gaussian ----------------
__global__ void init_kernel() {
    int t = threadIdx.x;
    if (t == 0) { d_total = 0.0; d_cnt = 0.0; }
    if (t < WIN) {
        double s = 0.0;
        #pragma unroll
        for (int i = 0; i < WIN; i++) {
            double d = (double)(i - WIN/2);
            s += exp(-d*d / (2.0*1.5*1.5));
        }
        double d = (double)(t - WIN/2);
        d_gw[t] = (float)(exp(-d*d / (2.0*1.5*1.5)) / s);
    }
}

// ---------------- crop+resize: one block per (batch, box) ----------------
__global__ void crop_kernel(const float* __restrict__ gt,
                            const float* __restrict__ pr,
                            const float* __restrict__ imgs) {
    int idx = blockIdx.x;
    int b = idx / (GG + PP);
    int j = idx % (GG + PP);
    const float* box;
    float* out;
    if (j < GG) { box = gt + (size_t)(b*GG + j)*4; out = d_gt_patch + (size_t)(b*GG + j)*3*NPIX; }
    else        { int p = j - GG; box = pr + (size_t)(b*PP + p)*4; out = d_pr_patch + (size_t)(b*PP + p)*3*NPIX; }

    float bx = box[0], by = box[1], bw = box[2], bh = box[3];
    float x0 = floorf(bx), y0 = floorf(by);
    float w  = floorf(bx + bw) - x0;
    float h  = floorf(by + bh) - y0;

    __shared__ int   s_ylo[SZ], s_yhi[SZ], s_xlo[SZ], s_xhi[SZ];
    __shared__ float s_wy[SZ],  s_wx[SZ];
    int t = threadIdx.x;
    if (t < SZ) {
        float hs = h / (float)SZ;
        float hm = fmaxf(h - 1.0f, 0.0f);
        float ys = fminf(fmaxf(((float)t + 0.5f) * hs - 0.5f, 0.0f), hm);
        float yf = floorf(ys);
        s_wy[t] = ys - yf;
        float ylo = yf + y0;
        float yhi = fminf(yf + 1.0f, hm) + y0;
        s_ylo[t] = (int)fminf(fmaxf(ylo, 0.0f), (float)(IMH - 1));
        s_yhi[t] = (int)fminf(fmaxf(yhi, 0.0f), (float)(IMH - 1));
    } else if (t < 2*SZ) {
        int i = t - SZ;
        float ws = w / (float)SZ;
        float wm = fmaxf(w - 1.0f, 0.0f);
        float xs = fminf(fmaxf(((float)i + 0.5f) * ws - 0.5f, 0.0f), wm);
        float xf = floorf(xs);
        s_wx[i] = xs - xf;
        float xlo = xf + x0;
        float xhi = fminf(xf + 1.0f, wm) + x0;
        s_xlo[i] = (int)fminf(fmaxf(xlo, 0.0f), (float)(IMW - 1));
        s_xhi[i] = (int)fminf(fmaxf(xhi, 0.0f), (float)(IMW - 1));
    }
    __syncthreads();

    const float* imb = imgs + (size_t)b * 3 * IMH * IMW;
    for (int px = t; px < 3*NPIX; px += blockDim.x) {
        int c   = px / NPIX;
        int r   = (px / SZ) % SZ;
        int col = px % SZ;
        const float* imc = imb + (size_t)c * IMH * IMW;
        int ylo = s_ylo[r], yhi = s_yhi[r];
        int xlo = s_xlo[col], xhi = s_xhi[col];
        float wx = s_wx[col], wy = s_wy[r];
        float tl = imc[(size_t)ylo*IMW + xlo];
        float tr = imc[(size_t)ylo*IMW + xhi];
        float bl = imc[(size_t)yhi*IMW + xlo];
        float br = imc[(size_t)yhi*IMW + xhi];
        float top = tl * (1.0f - wx) + tr * wx;
        float bot = bl * (1.0f - wx) + br * wx;
        out[px] = top * (1.0f - wy) + bot * wy;
    }
}

// ---------------- per-pair SSIM+L1: one block per (b,g,p); early-exit if unmasked ----------------
__global__ void pair_kernel(const float* __restrict__ gt,
                            const float* __restrict__ pr) {
    int idx = blockIdx.x;
    int b   = idx / (GG*PP);
    int rem = idx % (GG*PP);
    int g   = rem / PP;
    int p   = rem % PP;

    const float* gb = gt + (size_t)(b*GG + g)*4;
    const float* pb = pr + (size_t)(b*PP + p)*4;

    // IoU in f32, same op order as reference
    float gx = gb[0], gy = gb[1], gw_ = gb[2], gh_ = gb[3];
    float px_ = pb[0], py_ = pb[1], pw_ = pb[2], ph_ = pb[3];
    float tlx = fmaxf(gx - gw_*0.5f, px_ - pw_*0.5f);
    float tly = fmaxf(gy - gh_*0.5f, py_ - ph_*0.5f);
    float brx = fminf(gx + gw_*0.5f, px_ + pw_*0.5f);
    float bry = fminf(gy + gh_*0.5f, py_ + ph_*0.5f);
    float en  = ((tlx < brx) && (tly < bry)) ? 1.0f : 0.0f;
    float ai  = (brx - tlx) * (bry - tly) * en;
    float ag  = gw_ * gh_;
    float ap  = pw_ * ph_;
    float iou = ai / (ag + ap - ai + 1e-16f);
    bool mask = (iou > 0.3f) && (pw_ > 2.0f) && (ph_ > 2.0f);
    if (!mask) return;

    int t = threadIdx.x;
    if (t == 0) atomicAdd(&d_cnt, 1.0);

    __shared__ float sx[NPIX], sy[NPIX];
    __shared__ float Hb[5][NPIX];
    __shared__ float gwv[WIN];
    __shared__ float sred[8];
    if (t < WIN) gwv[t] = d_gw[t];

    const float* xpatch = d_pr_patch + (size_t)(b*PP + p)*3*NPIX;
    const float* ypatch = d_gt_patch + (size_t)(b*GG + g)*3*NPIX;

    const float C1 = 6.5025f;    // (0.01*255)^2
    const float C2 = 58.5225f;   // (0.03*255)^2
    float acc = 0.0f;

    for (int c = 0; c < 3; c++) {
        __syncthreads();  // protect smem reuse across channel iterations (+ gwv on first)
        for (int k = t; k < NPIX; k += 256) {
            sx[k] = xpatch[c*NPIX + k];
            sy[k] = ypatch[c*NPIX + k];
        }
        __syncthreads();

        // horizontal separable pass, zero-padded SAME, 5 fields {x,y,xx,yy,xy}
        for (int k = t; k < NPIX; k += 256) {
            int r = k >> 5, col = k & 31;
            int base = r * SZ;
            float h0=0.f,h1=0.f,h2=0.f,h3=0.f,h4=0.f;
            #pragma unroll
            for (int j = 0; j < WIN; j++) {
                int cc = col + j - WIN/2;
                if (cc >= 0 && cc < SZ) {
                    float wv = gwv[j];
                    float xv = sx[base + cc], yv = sy[base + cc];
                    h0 += wv * xv;
                    h1 += wv * yv;
                    h2 += wv * xv * xv;
                    h3 += wv * yv * yv;
                    h4 += wv * xv * yv;
                }
            }
            Hb[0][k]=h0; Hb[1][k]=h1; Hb[2][k]=h2; Hb[3][k]=h3; Hb[4][k]=h4;
        }
        __syncthreads();

        // vertical pass + SSIM + L1
        for (int k = t; k < NPIX; k += 256) {
            int r = k >> 5, col = k & 31;
            float v0=0.f,v1=0.f,v2=0.f,v3=0.f,v4=0.f;
            #pragma unroll
            for (int j = 0; j < WIN; j++) {
                int rr = r + j - WIN/2;
                if (rr >= 0 && rr < SZ) {
                    float wv = gwv[j];
                    int kk = rr * SZ + col;
                    v0 += wv * Hb[0][kk];
                    v1 += wv * Hb[1][kk];
                    v2 += wv * Hb[2][kk];
                    v3 += wv * Hb[3][kk];
                    v4 += wv * Hb[4][kk];
                }
            }
            float mu1 = v0, mu2 = v1;
            float mu1sq = mu1*mu1, mu2sq = mu2*mu2, mu12 = mu1*mu2;
            float s1  = v2 - mu1sq;
            float s2  = v3 - mu2sq;
            float s12 = v4 - mu12;
            float ssim = ((2.0f*mu12 + C1) * (2.0f*s12 + C2))
                       / ((mu1sq + mu2sq + C1) * (s1 + s2 + C2));
            float xv = sx[k], yv = sy[k];
            acc += fabsf(xv * (1.0f/255.0f) - yv * (1.0f/255.0f)) + (1.0f - ssim);
        }
    }

    // block reduce (8 warps)
    #pragma unroll
    for (int o = 16; o > 0; o >>= 1) acc += __shfl_down_sync(0xffffffffu, acc, o);
    if ((t & 31) == 0) sred[t >> 5] = acc;
    __syncthreads();
    if (t < 8) {
        float v = sred[t];
        #pragma unroll
        for (int o = 4; o > 0; o >>= 1) v += __shfl_down_sync(0xffu, v, o);
        if (t == 0) atomicAdd(&d_total, (double)v);
    }
}

// ---------------- finalize ----------------
__global__ void final_kernel(float* __restrict__ out) {
    double cnt = d_cnt * (double)(3*NPIX);
    out[0] = (cnt > 0.0) ? (float)(d_total / fmax(cnt, 1.0)) : 0.0f;
}

extern "C" void kernel_launch(void* const* d_in, const int* in_sizes, int n_in,
                              void* d_out, int out_size) {
    const float* gt   = (const float*)d_in[0];
    const float* pr   = (const float*)d_in[1];
    const float* imgs = (const float*)d_in[2];
    float* out = (float*)d_out;

    init_kernel<<<1, 32>>>();
    crop_kernel<<<BB*(GG+PP), 256>>>(gt, pr, imgs);
    pair_kernel<<<BB*GG*PP, 256>>>(gt, pr);
    final_kernel<<<1, 1>>>(out);
}

// round 2
// speedup vs baseline: 1.0259x; 1.0259x over previous
#include <cuda_runtime.h>
#include <math.h>

#define BB 8
#define GG 16
#define PP 64
#define IMH 640
#define IMW 640
#define SZ 32
#define NPIX (SZ*SZ)
#define WIN 11
#define NBLOCKS (BB*PP)

__device__ double d_total = 0.0;
__device__ double d_cnt   = 0.0;
__device__ unsigned int d_done = 0;

// Per-axis bilinear sampling coordinates (same arithmetic order as reference)
__device__ __forceinline__ void setup_axis(float origin, float len, int maxdim, int i,
                                           int* lo, int* hi, float* wgt) {
    float scale = len / (float)SZ;
    float lm = fmaxf(len - 1.0f, 0.0f);
    float s  = fminf(fmaxf(((float)i + 0.5f) * scale - 0.5f, 0.0f), lm);
    float sf = floorf(s);
    wgt[i] = s - sf;
    float vlo = sf + origin;
    float vhi = fminf(sf + 1.0f, lm) + origin;
    lo[i] = (int)fminf(fmaxf(vlo, 0.0f), (float)(maxdim - 1));
    hi[i] = (int)fminf(fmaxf(vhi, 0.0f), (float)(maxdim - 1));
}

__device__ __forceinline__ void setup_coords(const float* box, int* ylo, int* yhi, float* wy,
                                             int* xlo, int* xhi, float* wx, int t) {
    float bx = box[0], by = box[1], bw = box[2], bh = box[3];
    float x0 = floorf(bx), y0 = floorf(by);
    float w  = floorf(bx + bw) - x0;
    float h  = floorf(by + bh) - y0;
    if (t < SZ)            setup_axis(y0, h, IMH, t,       ylo, yhi, wy);
    else if (t < 2*SZ)     setup_axis(x0, w, IMW, t - SZ,  xlo, xhi, wx);
}

__device__ __forceinline__ void do_crop(const float* __restrict__ imb,
                                        const int* ylo, const int* yhi,
                                        const int* xlo, const int* xhi,
                                        const float* wy, const float* wx,
                                        float* out, int t) {
    for (int px = t; px < 3*NPIX; px += 256) {
        int c   = px / NPIX;
        int r   = (px / SZ) % SZ;
        int col = px % SZ;
        const float* imc = imb + (size_t)c * IMH * IMW;
        int yl = ylo[r], yh = yhi[r];
        int xl = xlo[col], xh = xhi[col];
        float ww = wx[col], wv = wy[r];
        float tl = imc[(size_t)yl*IMW + xl];
        float tr = imc[(size_t)yl*IMW + xh];
        float bl = imc[(size_t)yh*IMW + xl];
        float br = imc[(size_t)yh*IMW + xh];
        float top = tl * (1.0f - ww) + tr * ww;
        float bot = bl * (1.0f - ww) + br * ww;
        out[px] = top * (1.0f - wv) + bot * wv;
    }
}

__global__ void __launch_bounds__(256)
fused_kernel(const float* __restrict__ gt,
             const float* __restrict__ pr,
             const float* __restrict__ imgs,
             float* __restrict__ out) {
    int b = blockIdx.x / PP;
    int p = blockIdx.x % PP;
    int t = threadIdx.x;

    __shared__ float s_gw[WIN];
    __shared__ int   s_list[GG];
    __shared__ int   s_nm;
    __shared__ int   pylo[SZ], pyhi[SZ], pxlo[SZ], pxhi[SZ];
    __shared__ float pwy[SZ],  pwx[SZ];
    __shared__ int   gylo[SZ], gyhi[SZ], gxlo[SZ], gxhi[SZ];
    __shared__ float gwy[SZ],  gwx[SZ];
    __shared__ float s_pp[3*NPIX];   // pred patch (x)
    __shared__ float s_gp[3*NPIX];   // gt patch  (y)
    __shared__ float Hb[5][NPIX];
    __shared__ float sred[8];
    __shared__ bool  s_last;

    // gaussian window (double exp + normalize, matches numpy)
    if (t < WIN) {
        double s = 0.0;
        #pragma unroll
        for (int i = 0; i < WIN; i++) {
            double d = (double)(i - WIN/2);
            s += exp(-d*d / 4.5);
        }
        double d = (double)(t - WIN/2);
        s_gw[t] = (float)(exp(-d*d / 4.5) / s);
    }
    if (t == 0) s_nm = 0;
    __syncthreads();

    // IoU masks for this pred against all 16 gts
    const float* pb = pr + (size_t)(b*PP + p)*4;
    float px_ = pb[0], py_ = pb[1], pw_ = pb[2], ph_ = pb[3];
    if (t < GG) {
        const float* gb = gt + (size_t)(b*GG + t)*4;
        float gx = gb[0], gy = gb[1], gw_ = gb[2], gh_ = gb[3];
        float tlx = fmaxf(gx - gw_*0.5f, px_ - pw_*0.5f);
        float tly = fmaxf(gy - gh_*0.5f, py_ - ph_*0.5f);
        float brx = fminf(gx + gw_*0.5f, px_ + pw_*0.5f);
        float bry = fminf(gy + gh_*0.5f, py_ + ph_*0.5f);
        float en  = ((tlx < brx) && (tly < bry)) ? 1.0f : 0.0f;
        float ai  = (brx - tlx) * (bry - tly) * en;
        float iou = ai / (gw_*gh_ + pw_*ph_ - ai + 1e-16f);
        if ((iou > 0.3f) && (pw_ > 2.0f) && (ph_ > 2.0f)) {
            int idx = atomicAdd(&s_nm, 1);
            s_list[idx] = t;
        }
    }
    __syncthreads();
    int nm = s_nm;

    if (nm > 0) {
        const float* imb = imgs + (size_t)b * 3 * IMH * IMW;
        const float C1 = 6.5025f;    // (0.01*255)^2
        const float C2 = 58.5225f;   // (0.03*255)^2
        float accf = 0.0f;

        // pred coords + crop (once per block)
        setup_coords(pb, pylo, pyhi, pwy, pxlo, pxhi, pwx, t);
        __syncthreads();
        do_crop(imb, pylo, pyhi, pxlo, pxhi, pwy, pwx, s_pp, t);
        // no sync needed yet: covered by syncs below before first conv read

        for (int m = 0; m < nm; m++) {
            int g = s_list[m];
            const float* gb = gt + (size_t)(b*GG + g)*4;
            setup_coords(gb, gylo, gyhi, gwy, gxlo, gxhi, gwx, t);
            __syncthreads();
            do_crop(imb, gylo, gyhi, gxlo, gxhi, gwy, gwx, s_gp, t);
            __syncthreads();   // gt + pred patches ready

            for (int c = 0; c < 3; c++) {
                const float* sx = s_pp + c*NPIX;
                const float* sy = s_gp + c*NPIX;

                // horizontal separable pass (zero-padded SAME), 5 fields
                for (int k = t; k < NPIX; k += 256) {
                    int r = k >> 5, col = k & 31;
                    int base = r * SZ;
                    float h0=0.f,h1=0.f,h2=0.f,h3=0.f,h4=0.f;
                    #pragma unroll
                    for (int j = 0; j < WIN; j++) {
                        int cc = col + j - WIN/2;
                        if (cc >= 0 && cc < SZ) {
                            float wv = s_gw[j];
                            float xv = sx[base + cc], yv = sy[base + cc];
                            h0 += wv * xv;
                            h1 += wv * yv;
                            h2 += wv * xv * xv;
                            h3 += wv * yv * yv;
                            h4 += wv * xv * yv;
                        }
                    }
                    Hb[0][k]=h0; Hb[1][k]=h1; Hb[2][k]=h2; Hb[3][k]=h3; Hb[4][k]=h4;
                }
                __syncthreads();

                // vertical pass + SSIM + L1
                for (int k = t; k < NPIX; k += 256) {
                    int r = k >> 5, col = k & 31;
                    float v0=0.f,v1=0.f,v2=0.f,v3=0.f,v4=0.f;
                    #pragma unroll
                    for (int j = 0; j < WIN; j++) {
                        int rr = r + j - WIN/2;
                        if (rr >= 0 && rr < SZ) {
                            float wv = s_gw[j];
                            int kk = rr * SZ + col;
                            v0 += wv * Hb[0][kk];
                            v1 += wv * Hb[1][kk];
                            v2 += wv * Hb[2][kk];
                            v3 += wv * Hb[3][kk];
                            v4 += wv * Hb[4][kk];
                        }
                    }
                    float mu1 = v0, mu2 = v1;
                    float mu1sq = mu1*mu1, mu2sq = mu2*mu2, mu12 = mu1*mu2;
                    float s1  = v2 - mu1sq;
                    float s2  = v3 - mu2sq;
                    float s12 = v4 - mu12;
                    float ssim = ((2.0f*mu12 + C1) * (2.0f*s12 + C2))
                               / ((mu1sq + mu2sq + C1) * (s1 + s2 + C2));
                    float xv = sx[k], yv = sy[k];
                    accf += fabsf(xv * (1.0f/255.0f) - yv * (1.0f/255.0f)) + (1.0f - ssim);
                }
                __syncthreads();   // before Hb (and on last c: s_gp) is overwritten
            }
        }

        // block reduction
        #pragma unroll
        for (int o = 16; o > 0; o >>= 1) accf += __shfl_down_sync(0xffffffffu, accf, o);
        if ((t & 31) == 0) sred[t >> 5] = accf;
        __syncthreads();
        if (t < 8) {
            float v = sred[t];
            #pragma unroll
            for (int o = 4; o > 0; o >>= 1) v += __shfl_down_sync(0xffu, v, o);
            if (t == 0) {
                atomicAdd(&d_total, (double)v);
                atomicAdd(&d_cnt, (double)nm);
            }
        }
    }

    // completion counter: last block finalizes and resets accumulators
    __threadfence();
    if (t == 0) {
        unsigned prev = atomicAdd(&d_done, 1u);
        s_last = (prev == (unsigned)(NBLOCKS - 1));
    }
    __syncthreads();
    if (s_last && t == 0) {
        double cnt = d_cnt * (double)(3*NPIX);
        out[0] = (cnt > 0.0) ? (float)(d_total / fmax(cnt, 1.0)) : 0.0f;
        d_total = 0.0;
        d_cnt   = 0.0;
        d_done  = 0u;
    }
}

extern "C" void kernel_launch(void* const* d_in, const int* in_sizes, int n_in,
                              void* d_out, int out_size) {
    const float* gt   = (const float*)d_in[0];
    const float* pr   = (const float*)d_in[1];
    const float* imgs = (const float*)d_in[2];
    float* out = (float*)d_out;

    fused_kernel<<<NBLOCKS, 256>>>(gt, pr, imgs, out);
}

// round 3
// speedup vs baseline: 1.1672x; 1.1377x over previous
#include <cuda_runtime.h>
#include <math.h>

#define BB 8
#define GG 16
#define PP 64
#define IMH 640
#define IMW 640
#define SZ 32
#define WIN 11
#define NBLOCKS (BB*PP)

__device__ double d_total = 0.0;
__device__ double d_cnt   = 0.0;
__device__ unsigned int d_done = 0;

// Per-axis bilinear sampling coords, same arithmetic order as reference
__device__ __forceinline__ void axis_coord(float origin, float len, int maxdim, int i,
                                           int& lo, int& hi, float& wq) {
    float lm = fmaxf(len - 1.0f, 0.0f);
    float s  = fminf(fmaxf(((float)i + 0.5f) * (len / (float)SZ) - 0.5f, 0.0f), lm);
    float sf = floorf(s);
    wq = s - sf;
    float vlo = sf + origin;
    float vhi = fminf(sf + 1.0f, lm) + origin;
    lo = (int)fminf(fmaxf(vlo, 0.0f), (float)(maxdim - 1));
    hi = (int)fminf(fmaxf(vhi, 0.0f), (float)(maxdim - 1));
}

__device__ __forceinline__ float crop_px(const float* __restrict__ imc,
                                         int ylo, int yhi, float wy,
                                         int xlo, int xhi, float wx) {
    float tl = __ldg(imc + (size_t)ylo*IMW + xlo);
    float tr = __ldg(imc + (size_t)ylo*IMW + xhi);
    float bl = __ldg(imc + (size_t)yhi*IMW + xlo);
    float br = __ldg(imc + (size_t)yhi*IMW + xhi);
    float top = tl*(1.0f-wx) + tr*wx;
    float bot = bl*(1.0f-wx) + br*wx;
    return top*(1.0f-wy) + bot*wy;
}

__global__ void __launch_bounds__(512, 3)
fused_kernel(const float* __restrict__ gt,
             const float* __restrict__ pr,
             const float* __restrict__ imgs,
             float* __restrict__ out) {
    int t = threadIdx.x;
    int lane = t & 31;
    int warp = t >> 5;          // 0..15
    int r0 = warp * 2;          // this warp owns rows r0, r0+1; lane owns col=lane
    int b = blockIdx.x >> 6;    // / PP
    int p = blockIdx.x & 63;    // % PP

    __shared__ float s_gw[WIN];
    __shared__ int   s_list[GG];
    __shared__ int   s_nm;
    __shared__ float Hb[5][SZ*SZ];   // 20 KB
    __shared__ float sred[16];
    __shared__ bool  s_last;

    if (t == 0) s_nm = 0;
    if (t < WIN) {
        double ssum = 0.0;
        #pragma unroll
        for (int i = 0; i < WIN; i++) {
            double d = (double)(i - WIN/2);
            ssum += exp(-d*d / 4.5);
        }
        double d = (double)(t - WIN/2);
        s_gw[t] = (float)(exp(-d*d / 4.5) / ssum);
    }
    __syncthreads();

    // IoU mask of this pred against all 16 gts
    const float* pb = pr + (size_t)(b*PP + p)*4;
    float px_ = pb[0], py_ = pb[1], pw_ = pb[2], ph_ = pb[3];
    if (t < GG) {
        const float* gb = gt + (size_t)(b*GG + t)*4;
        float gx = gb[0], gy = gb[1], gw_ = gb[2], gh_ = gb[3];
        float tlx = fmaxf(gx - gw_*0.5f, px_ - pw_*0.5f);
        float tly = fmaxf(gy - gh_*0.5f, py_ - ph_*0.5f);
        float brx = fminf(gx + gw_*0.5f, px_ + pw_*0.5f);
        float bry = fminf(gy + gh_*0.5f, py_ + ph_*0.5f);
        float en  = ((tlx < brx) && (tly < bry)) ? 1.0f : 0.0f;
        float ai  = (brx - tlx) * (bry - tly) * en;
        float iou = ai / (gw_*gh_ + pw_*ph_ - ai + 1e-16f);
        if ((iou > 0.3f) && (pw_ > 2.0f) && (ph_ > 2.0f)) {
            int i = atomicAdd(&s_nm, 1);
            s_list[i] = t;
        }
    }
    __syncthreads();
    int nm = s_nm;

    if (nm > 0) {
        const float* imb = imgs + (size_t)b * 3 * IMH * IMW;
        const float C1 = 6.5025f;    // (0.01*255)^2
        const float C2 = 58.5225f;   // (0.03*255)^2
        float accf = 0.0f;

        // pred sampling coords (registers, per thread)
        float x0p = floorf(px_), y0p = floorf(py_);
        float wp  = floorf(px_ + pw_) - x0p;
        float hp  = floorf(py_ + ph_) - y0p;
        int pxlo, pxhi; float pwx;
        int pylo0, pyhi0; float pwy0;
        int pylo1, pyhi1; float pwy1;
        axis_coord(x0p, wp, IMW, lane, pxlo, pxhi, pwx);
        axis_coord(y0p, hp, IMH, r0,   pylo0, pyhi0, pwy0);
        axis_coord(y0p, hp, IMH, r0+1, pylo1, pyhi1, pwy1);

        for (int m = 0; m < nm; m++) {
            int g = s_list[m];
            const float* gb = gt + (size_t)(b*GG + g)*4;
            float gx = gb[0], gy = gb[1], gwd = gb[2], ghd = gb[3];
            float x0g = floorf(gx), y0g = floorf(gy);
            float wg  = floorf(gx + gwd) - x0g;
            float hg  = floorf(gy + ghd) - y0g;
            int gxlo, gxhi; float gwx;
            int gylo0, gyhi0; float gwy0;
            int gylo1, gyhi1; float gwy1;
            axis_coord(x0g, wg, IMW, lane, gxlo, gxhi, gwx);
            axis_coord(y0g, hg, IMH, r0,   gylo0, gyhi0, gwy0);
            axis_coord(y0g, hg, IMH, r0+1, gylo1, gyhi1, gwy1);

            for (int c = 0; c < 3; c++) {
                const float* imc = imb + (size_t)c * IMH * IMW;
                // crop this thread's 2 pred + 2 gt pixels into registers
                float x0v = crop_px(imc, pylo0, pyhi0, pwy0, pxlo, pxhi, pwx);
                float x1v = crop_px(imc, pylo1, pyhi1, pwy1, pxlo, pxhi, pwx);
                float y0v = crop_px(imc, gylo0, gyhi0, gwy0, gxlo, gxhi, gwx);
                float y1v = crop_px(imc, gylo1, gyhi1, gwy1, gxlo, gxhi, gwx);

                // horizontal pass via warp shuffles (row == warp lanes), zero-pad SAME
                #pragma unroll
                for (int rr = 0; rr < 2; rr++) {
                    float xv = rr ? x1v : x0v;
                    float yv = rr ? y1v : y0v;
                    float h0=0.f,h1=0.f,h2=0.f,h3=0.f,h4=0.f;
                    #pragma unroll
                    for (int d = -5; d <= 5; d++) {
                        float xs = __shfl_sync(0xffffffffu, xv, lane + d);
                        float ys = __shfl_sync(0xffffffffu, yv, lane + d);
                        if ((unsigned)(lane + d) < 32u) {
                            float wv = s_gw[d + 5];
                            h0 += wv * xs;
                            h1 += wv * ys;
                            h2 += wv * xs * xs;
                            h3 += wv * ys * ys;
                            h4 += wv * xs * ys;
                        }
                    }
                    int k = (r0 + rr) * SZ + lane;
                    Hb[0][k]=h0; Hb[1][k]=h1; Hb[2][k]=h2; Hb[3][k]=h3; Hb[4][k]=h4;
                }
                __syncthreads();

                // vertical pass: rows r0 and r0+1 share loads over rows r0-5..r0+6
                float v00=0.f,v01=0.f,v02=0.f,v03=0.f,v04=0.f;
                float v10=0.f,v11=0.f,v12=0.f,v13=0.f,v14=0.f;
                #pragma unroll
                for (int d = -5; d <= 6; d++) {
                    int rrw = r0 + d;
                    if (rrw >= 0 && rrw < SZ) {
                        int kk = rrw * SZ + lane;
                        float f0=Hb[0][kk], f1=Hb[1][kk], f2=Hb[2][kk], f3=Hb[3][kk], f4=Hb[4][kk];
                        if (d <= 5) {           // tap for output row r0 (offset d)
                            float wv = s_gw[d + 5];
                            v00+=wv*f0; v01+=wv*f1; v02+=wv*f2; v03+=wv*f3; v04+=wv*f4;
                        }
                        if (d >= -4) {          // tap for output row r0+1 (offset d-1)
                            float wv = s_gw[d + 4];
                            v10+=wv*f0; v11+=wv*f1; v12+=wv*f2; v13+=wv*f3; v14+=wv*f4;
                        }
                    }
                }

                // SSIM + L1 for the two pixels
                {
                    float mu1 = v00, mu2 = v01;
                    float mu1sq = mu1*mu1, mu2sq = mu2*mu2, mu12 = mu1*mu2;
                    float s1  = v02 - mu1sq;
                    float s2  = v03 - mu2sq;
                    float s12 = v04 - mu12;
                    float ssim = ((2.0f*mu12 + C1) * (2.0f*s12 + C2))
                               / ((mu1sq + mu2sq + C1) * (s1 + s2 + C2));
                    accf += fabsf(x0v*(1.0f/255.0f) - y0v*(1.0f/255.0f)) + (1.0f - ssim);
                }
                {
                    float mu1 = v10, mu2 = v11;
                    float mu1sq = mu1*mu1, mu2sq = mu2*mu2, mu12 = mu1*mu2;
                    float s1  = v12 - mu1sq;
                    float s2  = v13 - mu2sq;
                    float s12 = v14 - mu12;
                    float ssim = ((2.0f*mu12 + C1) * (2.0f*s12 + C2))
                               / ((mu1sq + mu2sq + C1) * (s1 + s2 + C2));
                    accf += fabsf(x1v*(1.0f/255.0f) - y1v*(1.0f/255.0f)) + (1.0f - ssim);
                }
                __syncthreads();   // before Hb overwritten next channel/gt
            }
        }

        // block reduction (16 warps)
        #pragma unroll
        for (int o = 16; o > 0; o >>= 1) accf += __shfl_down_sync(0xffffffffu, accf, o);
        if (lane == 0) sred[warp] = accf;
        __syncthreads();
        if (t < 16) {
            float v = sred[t];
            #pragma unroll
            for (int o = 8; o > 0; o >>= 1) v += __shfl_down_sync(0xffffu, v, o);
            if (t == 0) {
                atomicAdd(&d_total, (double)v);
                atomicAdd(&d_cnt, (double)nm);
            }
        }
    }

    // completion counter: last block finalizes and resets accumulators
    __threadfence();
    if (t == 0) {
        unsigned prev = atomicAdd(&d_done, 1u);
        s_last = (prev == (unsigned)(NBLOCKS - 1));
    }
    __syncthreads();
    if (s_last && t == 0) {
        double cnt = d_cnt * (double)(3*SZ*SZ);
        out[0] = (cnt > 0.0) ? (float)(d_total / fmax(cnt, 1.0)) : 0.0f;
        d_total = 0.0;
        d_cnt   = 0.0;
        d_done  = 0u;
    }
}

extern "C" void kernel_launch(void* const* d_in, const int* in_sizes, int n_in,
                              void* d_out, int out_size) {
    const float* gt   = (const float*)d_in[0];
    const float* pr   = (const float*)d_in[1];
    const float* imgs = (const float*)d_in[2];
    float* out = (float*)d_out;

    fused_kernel<<<NBLOCKS, 512>>>(gt, pr, imgs, out);
}

// round 4
// speedup vs baseline: 1.5599x; 1.3365x over previous
#include <cuda_runtime.h>
#include <math.h>

#define BB 8
#define GG 16
#define PP 64
#define IMH 640
#define IMW 640
#define SZ 32
#define WIN 11
#define NBLOCKS (BB*PP)

__device__ double d_total = 0.0;
__device__ double d_cnt   = 0.0;
__device__ unsigned int d_done = 0;

// Per-axis bilinear sampling coords, same arithmetic order as reference
__device__ __forceinline__ void axis_coord(float origin, float len, int maxdim, int i,
                                           int& lo, int& hi, float& wq) {
    float lm = fmaxf(len - 1.0f, 0.0f);
    float s  = fminf(fmaxf(((float)i + 0.5f) * (len / (float)SZ) - 0.5f, 0.0f), lm);
    float sf = floorf(s);
    wq = s - sf;
    float vlo = sf + origin;
    float vhi = fminf(sf + 1.0f, lm) + origin;
    lo = (int)fminf(fmaxf(vlo, 0.0f), (float)(maxdim - 1));
    hi = (int)fminf(fmaxf(vhi, 0.0f), (float)(maxdim - 1));
}

// Build the 8 int offsets (2 rows x 4 corners) + 3 weights for one box
struct CropCtx {
    int   o[8];            // tl0,tr0,bl0,br0, tl1,tr1,bl1,br1
    float wx, wy0, wy1;
};

__device__ __forceinline__ void make_ctx(const float* __restrict__ box,
                                         int lane, int r0, CropCtx& cx) {
    float bx = box[0], by = box[1], bw = box[2], bh = box[3];
    float x0 = floorf(bx), y0 = floorf(by);
    float w  = floorf(bx + bw) - x0;
    float h  = floorf(by + bh) - y0;
    int xlo, xhi, ylo0, yhi0, ylo1, yhi1;
    axis_coord(x0, w, IMW, lane, xlo, xhi, cx.wx);
    axis_coord(y0, h, IMH, r0,   ylo0, yhi0, cx.wy0);
    axis_coord(y0, h, IMH, r0+1, ylo1, yhi1, cx.wy1);
    cx.o[0] = ylo0*IMW + xlo;  cx.o[1] = ylo0*IMW + xhi;
    cx.o[2] = yhi0*IMW + xlo;  cx.o[3] = yhi0*IMW + xhi;
    cx.o[4] = ylo1*IMW + xlo;  cx.o[5] = ylo1*IMW + xhi;
    cx.o[6] = yhi1*IMW + xlo;  cx.o[7] = yhi1*IMW + xhi;
}

__device__ __forceinline__ float crop2(const float* __restrict__ imc,
                                       const int* o, float wx, float wy) {
    float tl = __ldg(imc + o[0]);
    float tr = __ldg(imc + o[1]);
    float bl = __ldg(imc + o[2]);
    float br = __ldg(imc + o[3]);
    float top = tl*(1.0f-wx) + tr*wx;
    float bot = bl*(1.0f-wx) + br*wx;
    return top*(1.0f-wy) + bot*wy;
}

__global__ void __launch_bounds__(512, 3)
fused_kernel(const float* __restrict__ gt,
             const float* __restrict__ pr,
             const float* __restrict__ imgs,
             float* __restrict__ out) {
    int t = threadIdx.x;
    int lane = t & 31;
    int warp = t >> 5;          // 0..15
    int r0 = warp * 2;          // warp owns rows r0, r0+1; lane owns col=lane
    int b = blockIdx.x >> 6;
    int p = blockIdx.x & 63;

    __shared__ float s_gw[WIN];
    __shared__ int   s_list[GG];
    __shared__ int   s_nm;
    __shared__ float Hb[2][5][SZ*SZ];   // double-buffered, 40 KB
    __shared__ float sred[16];
    __shared__ bool  s_last;

    if (t == 0) s_nm = 0;
    if (t < WIN) {
        // float expf: <=2ulp from the double-exp reference weights; tolerance 1e-3
        float ssum = 0.0f;
        #pragma unroll
        for (int i = 0; i < WIN; i++) {
            float d = (float)(i - WIN/2);
            ssum += expf(-d*d / 4.5f);
        }
        float d = (float)(t - WIN/2);
        s_gw[t] = expf(-d*d / 4.5f) / ssum;
    }
    __syncthreads();

    // IoU mask of this pred against all 16 gts
    const float* pb = pr + (size_t)(b*PP + p)*4;
    float px_ = pb[0], py_ = pb[1], pw_ = pb[2], ph_ = pb[3];
    if (t < GG) {
        const float* gb = gt + (size_t)(b*GG + t)*4;
        float gx = gb[0], gy = gb[1], gw_ = gb[2], gh_ = gb[3];
        float tlx = fmaxf(gx - gw_*0.5f, px_ - pw_*0.5f);
        float tly = fmaxf(gy - gh_*0.5f, py_ - ph_*0.5f);
        float brx = fminf(gx + gw_*0.5f, px_ + pw_*0.5f);
        float bry = fminf(gy + gh_*0.5f, py_ + ph_*0.5f);
        float en  = ((tlx < brx) && (tly < bry)) ? 1.0f : 0.0f;
        float ai  = (brx - tlx) * (bry - tly) * en;
        float iou = ai / (gw_*gh_ + pw_*ph_ - ai + 1e-16f);
        if ((iou > 0.3f) && (pw_ > 2.0f) && (ph_ > 2.0f)) {
            int i = atomicAdd(&s_nm, 1);
            s_list[i] = t;
        }
    }
    __syncthreads();
    int nm = s_nm;

    if (nm > 0) {
        const float* imb = imgs + (size_t)b * 3 * IMH * IMW;
        const float C1 = 6.5025f;    // (0.01*255)^2
        const float C2 = 58.5225f;   // (0.03*255)^2
        float accf = 0.0f;

        CropCtx pc;
        make_ctx(pb, lane, r0, pc);

        int iter = 0;
        for (int m = 0; m < nm; m++) {
            int g = s_list[m];
            CropCtx gc;
            make_ctx(gt + (size_t)(b*GG + g)*4, lane, r0, gc);

            for (int c = 0; c < 3; c++, iter++) {
                const float* imc = imb + (size_t)c * IMH * IMW;
                int buf = iter & 1;

                // crop 2 pred + 2 gt pixels into registers
                float x0v = crop2(imc, pc.o,     pc.wx, pc.wy0);
                float x1v = crop2(imc, pc.o + 4, pc.wx, pc.wy1);
                float y0v = crop2(imc, gc.o,     gc.wx, gc.wy0);
                float y1v = crop2(imc, gc.o + 4, gc.wx, gc.wy1);

                // horizontal pass via warp shuffles (row == warp), zero-pad SAME
                #pragma unroll
                for (int rr = 0; rr < 2; rr++) {
                    float xv = rr ? x1v : x0v;
                    float yv = rr ? y1v : y0v;
                    float h0=0.f,h1=0.f,h2=0.f,h3=0.f,h4=0.f;
                    #pragma unroll
                    for (int d = -5; d <= 5; d++) {
                        float xs = __shfl_sync(0xffffffffu, xv, lane + d);
                        float ys = __shfl_sync(0xffffffffu, yv, lane + d);
                        if ((unsigned)(lane + d) < 32u) {
                            float wv = s_gw[d + 5];
                            h0 += wv * xs;
                            h1 += wv * ys;
                            h2 += wv * xs * xs;
                            h3 += wv * ys * ys;
                            h4 += wv * xs * ys;
                        }
                    }
                    int k = (r0 + rr) * SZ + lane;
                    Hb[buf][0][k]=h0; Hb[buf][1][k]=h1; Hb[buf][2][k]=h2;
                    Hb[buf][3][k]=h3; Hb[buf][4][k]=h4;
                }
                __syncthreads();   // single barrier per iteration (double buffer)

                // vertical pass: rows r0 and r0+1 share loads over rows r0-5..r0+6
                float v00=0.f,v01=0.f,v02=0.f,v03=0.f,v04=0.f;
                float v10=0.f,v11=0.f,v12=0.f,v13=0.f,v14=0.f;
                #pragma unroll
                for (int d = -5; d <= 6; d++) {
                    int rrw = r0 + d;
                    if (rrw >= 0 && rrw < SZ) {
                        int kk = rrw * SZ + lane;
                        float f0=Hb[buf][0][kk], f1=Hb[buf][1][kk], f2=Hb[buf][2][kk];
                        float f3=Hb[buf][3][kk], f4=Hb[buf][4][kk];
                        if (d <= 5) {           // tap for output row r0
                            float wv = s_gw[d + 5];
                            v00+=wv*f0; v01+=wv*f1; v02+=wv*f2; v03+=wv*f3; v04+=wv*f4;
                        }
                        if (d >= -4) {          // tap for output row r0+1
                            float wv = s_gw[d + 4];
                            v10+=wv*f0; v11+=wv*f1; v12+=wv*f2; v13+=wv*f3; v14+=wv*f4;
                        }
                    }
                }

                // SSIM + L1 for the two pixels
                {
                    float mu1 = v00, mu2 = v01;
                    float mu1sq = mu1*mu1, mu2sq = mu2*mu2, mu12 = mu1*mu2;
                    float s1  = v02 - mu1sq;
                    float s2  = v03 - mu2sq;
                    float s12 = v04 - mu12;
                    float ssim = ((2.0f*mu12 + C1) * (2.0f*s12 + C2))
                               / ((mu1sq + mu2sq + C1) * (s1 + s2 + C2));
                    accf += fabsf(x0v*(1.0f/255.0f) - y0v*(1.0f/255.0f)) + (1.0f - ssim);
                }
                {
                    float mu1 = v10, mu2 = v11;
                    float mu1sq = mu1*mu1, mu2sq = mu2*mu2, mu12 = mu1*mu2;
                    float s1  = v12 - mu1sq;
                    float s2  = v13 - mu2sq;
                    float s12 = v14 - mu12;
                    float ssim = ((2.0f*mu12 + C1) * (2.0f*s12 + C2))
                               / ((mu1sq + mu2sq + C1) * (s1 + s2 + C2));
                    accf += fabsf(x1v*(1.0f/255.0f) - y1v*(1.0f/255.0f)) + (1.0f - ssim);
                }
                // no trailing barrier: next iteration writes the other buffer
            }
        }

        // block reduction (16 warps)
        #pragma unroll
        for (int o = 16; o > 0; o >>= 1) accf += __shfl_down_sync(0xffffffffu, accf, o);
        if (lane == 0) sred[warp] = accf;
        __syncthreads();
        if (t < 16) {
            float v = sred[t];
            #pragma unroll
            for (int o = 8; o > 0; o >>= 1) v += __shfl_down_sync(0xffffu, v, o);
            if (t == 0) {
                atomicAdd(&d_total, (double)v);
                atomicAdd(&d_cnt, (double)nm);
            }
        }
    }

    // completion counter: last block finalizes and resets accumulators
    __threadfence();
    if (t == 0) {
        unsigned prev = atomicAdd(&d_done, 1u);
        s_last = (prev == (unsigned)(NBLOCKS - 1));
    }
    __syncthreads();
    if (s_last && t == 0) {
        double cnt = d_cnt * (double)(3*SZ*SZ);
        out[0] = (cnt > 0.0) ? (float)(d_total / fmax(cnt, 1.0)) : 0.0f;
        d_total = 0.0;
        d_cnt   = 0.0;
        d_done  = 0u;
    }
}

extern "C" void kernel_launch(void* const* d_in, const int* in_sizes, int n_in,
                              void* d_out, int out_size) {
    const float* gt   = (const float*)d_in[0];
    const float* pr   = (const float*)d_in[1];
    const float* imgs = (const float*)d_in[2];
    float* out = (float*)d_out;

    fused_kernel<<<NBLOCKS, 512>>>(gt, pr, imgs, out);
}

// round 5
// speedup vs baseline: 1.7369x; 1.1134x over previous
#include <cuda_runtime.h>
#include <math.h>

#define BB 8
#define GG 16
#define PP 64
#define IMH 640
#define IMW 640
#define SZ 32
#define WIN 11
#define NBLOCKS (BB*PP*3)

__device__ double d_total = 0.0;
__device__ double d_cnt   = 0.0;
__device__ unsigned int d_done = 0;

// Per-axis bilinear sampling coords, same arithmetic order as reference
__device__ __forceinline__ void axis_coord(float origin, float len, int maxdim, int i,
                                           int& lo, int& hi, float& wq) {
    float lm = fmaxf(len - 1.0f, 0.0f);
    float s  = fminf(fmaxf(((float)i + 0.5f) * (len / (float)SZ) - 0.5f, 0.0f), lm);
    float sf = floorf(s);
    wq = s - sf;
    float vlo = sf + origin;
    float vhi = fminf(sf + 1.0f, lm) + origin;
    lo = (int)fminf(fmaxf(vlo, 0.0f), (float)(maxdim - 1));
    hi = (int)fminf(fmaxf(vhi, 0.0f), (float)(maxdim - 1));
}

struct CropCtx {
    int   o[8];            // tl0,tr0,bl0,br0, tl1,tr1,bl1,br1
    float wx, wy0, wy1;
};

__device__ __forceinline__ void make_ctx(const float* __restrict__ box,
                                         int lane, int r0, CropCtx& cx) {
    float bx = box[0], by = box[1], bw = box[2], bh = box[3];
    float x0 = floorf(bx), y0 = floorf(by);
    float w  = floorf(bx + bw) - x0;
    float h  = floorf(by + bh) - y0;
    int xlo, xhi, ylo0, yhi0, ylo1, yhi1;
    axis_coord(x0, w, IMW, lane, xlo, xhi, cx.wx);
    axis_coord(y0, h, IMH, r0,   ylo0, yhi0, cx.wy0);
    axis_coord(y0, h, IMH, r0+1, ylo1, yhi1, cx.wy1);
    cx.o[0] = ylo0*IMW + xlo;  cx.o[1] = ylo0*IMW + xhi;
    cx.o[2] = yhi0*IMW + xlo;  cx.o[3] = yhi0*IMW + xhi;
    cx.o[4] = ylo1*IMW + xlo;  cx.o[5] = ylo1*IMW + xhi;
    cx.o[6] = yhi1*IMW + xlo;  cx.o[7] = yhi1*IMW + xhi;
}

__device__ __forceinline__ float crop2(const float* __restrict__ imc,
                                       const int* o, float wx, float wy) {
    float tl = __ldg(imc + o[0]);
    float tr = __ldg(imc + o[1]);
    float bl = __ldg(imc + o[2]);
    float br = __ldg(imc + o[3]);
    float top = tl*(1.0f-wx) + tr*wx;
    float bot = bl*(1.0f-wx) + br*wx;
    return top*(1.0f-wy) + bot*wy;
}

__global__ void __launch_bounds__(512, 3)
fused_kernel(const float* __restrict__ gt,
             const float* __restrict__ pr,
             const float* __restrict__ imgs,
             float* __restrict__ out) {
    int t = threadIdx.x;
    int lane = t & 31;
    int warp = t >> 5;          // 0..15
    int r0 = warp * 2;          // warp owns rows r0, r0+1; lane owns col=lane
    int idx = blockIdx.x;
    int c  = idx % 3;           // channel handled by this block
    int pi = idx / 3;
    int b  = pi >> 6;
    int p  = pi & 63;

    __shared__ float s_gw[WIN];
    __shared__ int   s_list[GG];
    __shared__ int   s_nm;
    __shared__ float Hb[2][4][SZ*SZ];   // double-buffered, 4 fields, 32 KB
    __shared__ float sred[16];
    __shared__ bool  s_last;

    if (t == 0) s_nm = 0;
    if (t < WIN) {
        float ssum = 0.0f;
        #pragma unroll
        for (int i = 0; i < WIN; i++) {
            float d = (float)(i - WIN/2);
            ssum += expf(-d*d / 4.5f);
        }
        float d = (float)(t - WIN/2);
        s_gw[t] = expf(-d*d / 4.5f) / ssum;
    }
    __syncthreads();

    // IoU mask of this pred against all 16 gts
    const float* pb = pr + (size_t)(b*PP + p)*4;
    float px_ = pb[0], py_ = pb[1], pw_ = pb[2], ph_ = pb[3];
    if (t < GG) {
        const float* gb = gt + (size_t)(b*GG + t)*4;
        float gx = gb[0], gy = gb[1], gw_ = gb[2], gh_ = gb[3];
        float tlx = fmaxf(gx - gw_*0.5f, px_ - pw_*0.5f);
        float tly = fmaxf(gy - gh_*0.5f, py_ - ph_*0.5f);
        float brx = fminf(gx + gw_*0.5f, px_ + pw_*0.5f);
        float bry = fminf(gy + gh_*0.5f, py_ + ph_*0.5f);
        float en  = ((tlx < brx) && (tly < bry)) ? 1.0f : 0.0f;
        float ai  = (brx - tlx) * (bry - tly) * en;
        float iou = ai / (gw_*gh_ + pw_*ph_ - ai + 1e-16f);
        if ((iou > 0.3f) && (pw_ > 2.0f) && (ph_ > 2.0f)) {
            int i = atomicAdd(&s_nm, 1);
            s_list[i] = t;
        }
    }
    __syncthreads();
    int nm = s_nm;

    if (nm > 0) {
        const float* imc = imgs + ((size_t)b * 3 + c) * IMH * IMW;
        const float C1 = 6.5025f;    // (0.01*255)^2
        const float C2 = 58.5225f;   // (0.03*255)^2
        float accf = 0.0f;

        // pred crop: channel is fixed for this block -> hoist out of gt loop
        CropCtx pc;
        make_ctx(pb, lane, r0, pc);
        float x0v = crop2(imc, pc.o,     pc.wx, pc.wy0);
        float x1v = crop2(imc, pc.o + 4, pc.wx, pc.wy1);

        for (int m = 0; m < nm; m++) {
            int buf = m & 1;
            CropCtx gc;
            make_ctx(gt + (size_t)(b*GG + s_list[m])*4, lane, r0, gc);
            float y0v = crop2(imc, gc.o,     gc.wx, gc.wy0);
            float y1v = crop2(imc, gc.o + 4, gc.wx, gc.wy1);

            // horizontal pass via warp shuffles, zero-pad SAME, 4 fields
            #pragma unroll
            for (int rr = 0; rr < 2; rr++) {
                float xv = rr ? x1v : x0v;
                float yv = rr ? y1v : y0v;
                float h0=0.f,h1=0.f,h2=0.f,h3=0.f;
                #pragma unroll
                for (int d = -5; d <= 5; d++) {
                    float xs = __shfl_sync(0xffffffffu, xv, lane + d);
                    float ys = __shfl_sync(0xffffffffu, yv, lane + d);
                    if ((unsigned)(lane + d) < 32u) {
                        float wv = s_gw[d + 5];
                        h0 += wv * xs;
                        h1 += wv * ys;
                        h2 += wv * (xs * xs + ys * ys);
                        h3 += wv * (xs * ys);
                    }
                }
                int k = (r0 + rr) * SZ + lane;
                Hb[buf][0][k]=h0; Hb[buf][1][k]=h1; Hb[buf][2][k]=h2; Hb[buf][3][k]=h3;
            }
            __syncthreads();   // single barrier per gt (double buffer)

            // vertical pass: rows r0 and r0+1 share loads over rows r0-5..r0+6
            float v00=0.f,v01=0.f,v02=0.f,v03=0.f;
            float v10=0.f,v11=0.f,v12=0.f,v13=0.f;
            #pragma unroll
            for (int d = -5; d <= 6; d++) {
                int rrw = r0 + d;
                if (rrw >= 0 && rrw < SZ) {
                    int kk = rrw * SZ + lane;
                    float f0=Hb[buf][0][kk], f1=Hb[buf][1][kk];
                    float f2=Hb[buf][2][kk], f3=Hb[buf][3][kk];
                    if (d <= 5) {            // tap for output row r0
                        float wv = s_gw[d + 5];
                        v00+=wv*f0; v01+=wv*f1; v02+=wv*f2; v03+=wv*f3;
                    }
                    if (d >= -4) {           // tap for output row r0+1
                        float wv = s_gw[d + 4];
                        v10+=wv*f0; v11+=wv*f1; v12+=wv*f2; v13+=wv*f3;
                    }
                }
            }

            // SSIM + L1 for the two pixels
            {
                float mu1 = v00, mu2 = v01;
                float mu1sq = mu1*mu1, mu2sq = mu2*mu2, mu12 = mu1*mu2;
                float sS  = v02 - mu1sq - mu2sq;   // s1 + s2
                float s12 = v03 - mu12;
                float ssim = ((2.0f*mu12 + C1) * (2.0f*s12 + C2))
                           / ((mu1sq + mu2sq + C1) * (sS + C2));
                accf += fabsf(x0v*(1.0f/255.0f) - y0v*(1.0f/255.0f)) + (1.0f - ssim);
            }
            {
                float mu1 = v10, mu2 = v11;
                float mu1sq = mu1*mu1, mu2sq = mu2*mu2, mu12 = mu1*mu2;
                float sS  = v12 - mu1sq - mu2sq;
                float s12 = v13 - mu12;
                float ssim = ((2.0f*mu12 + C1) * (2.0f*s12 + C2))
                           / ((mu1sq + mu2sq + C1) * (sS + C2));
                accf += fabsf(x1v*(1.0f/255.0f) - y1v*(1.0f/255.0f)) + (1.0f - ssim);
            }
            // no trailing barrier: next gt writes the other buffer
        }

        // block reduction (16 warps)
        #pragma unroll
        for (int o = 16; o > 0; o >>= 1) accf += __shfl_down_sync(0xffffffffu, accf, o);
        if (lane == 0) sred[warp] = accf;
        __syncthreads();
        if (t < 16) {
            float v = sred[t];
            #pragma unroll
            for (int o = 8; o > 0; o >>= 1) v += __shfl_down_sync(0xffffu, v, o);
            if (t == 0) {
                atomicAdd(&d_total, (double)v);
                if (c == 0) atomicAdd(&d_cnt, (double)nm);  // count each pair once
            }
        }
    }

    // completion counter: last block finalizes and resets accumulators
    __threadfence();
    if (t == 0) {
        unsigned prev = atomicAdd(&d_done, 1u);
        s_last = (prev == (unsigned)(NBLOCKS - 1));
    }
    __syncthreads();
    if (s_last && t == 0) {
        double cnt = d_cnt * (double)(3*SZ*SZ);
        out[0] = (cnt > 0.0) ? (float)(d_total / fmax(cnt, 1.0)) : 0.0f;
        d_total = 0.0;
        d_cnt   = 0.0;
        d_done  = 0u;
    }
}

extern "C" void kernel_launch(void* const* d_in, const int* in_sizes, int n_in,
                              void* d_out, int out_size) {
    const float* gt   = (const float*)d_in[0];
    const float* pr   = (const float*)d_in[1];
    const float* imgs = (const float*)d_in[2];
    float* out = (float*)d_out;

    fused_kernel<<<NBLOCKS, 512>>>(gt, pr, imgs, out);
}